// round 2
// baseline (speedup 1.0000x reference)
#include <cuda_runtime.h>

#define M1 768
#define M2 768
#define HID 1024
#define ATTN 256

// Scratch (no cudaMalloc allowed)
__device__ float g_x1[M1 * ATTN];
__device__ float g_x2[M2 * ATTN];
__device__ float g_rowsum[M1];
__device__ float g_colsum[M2];

__device__ __forceinline__ float tanh_fast(float x) {
    float r;
    asm("tanh.approx.f32 %0, %1;" : "=f"(r) : "f"(x));
    return r;
}

// ---------------------------------------------------------------------------
// Kernel A: x = h @ W^T + b for both inputs (z = 0 -> x1, z = 1 -> x2).
// Tile 64(m) x 64(a), K-chunk 32, 256 threads, 4x4 per thread.
// Block (0,0,z) additionally zeroes the row/col accumulators.
// ---------------------------------------------------------------------------
__global__ __launch_bounds__(256) void proj_kernel(
    const float* __restrict__ h1, const float* __restrict__ W1, const float* __restrict__ b1,
    const float* __restrict__ h2, const float* __restrict__ W2, const float* __restrict__ b2)
{
    const int z = blockIdx.z;
    const float* __restrict__ h = z ? h2 : h1;
    const float* __restrict__ W = z ? W2 : W1;
    const float* __restrict__ b = z ? b2 : b1;
    float* __restrict__ xout = z ? g_x2 : g_x1;

    const int tid = threadIdx.y * 16 + threadIdx.x;

    if (blockIdx.x == 0 && blockIdx.y == 0) {
        float* t = z ? g_colsum : g_rowsum;
        const int n = z ? M2 : M1;
        for (int i = tid; i < n; i += 256) t[i] = 0.0f;
    }

    __shared__ float hs[32][65];
    __shared__ float ws[32][65];

    const int m0 = blockIdx.y * 64;
    const int a0 = blockIdx.x * 64;

    float acc[4][4];
#pragma unroll
    for (int i = 0; i < 4; i++)
#pragma unroll
        for (int j = 0; j < 4; j++) acc[i][j] = 0.0f;

    for (int k0 = 0; k0 < HID; k0 += 32) {
        __syncthreads();
#pragma unroll
        for (int it = 0; it < 8; it++) {
            int idx = tid + it * 256;
            int r = idx >> 5;       // 0..63
            int c = idx & 31;       // 0..31 (coalesced over k)
            hs[c][r] = h[(m0 + r) * HID + k0 + c];
            ws[c][r] = W[(a0 + r) * HID + k0 + c];
        }
        __syncthreads();
#pragma unroll 8
        for (int k = 0; k < 32; k++) {
            float hv[4], wv[4];
#pragma unroll
            for (int i = 0; i < 4; i++) hv[i] = hs[k][threadIdx.y + 16 * i];
#pragma unroll
            for (int j = 0; j < 4; j++) wv[j] = ws[k][threadIdx.x + 16 * j];
#pragma unroll
            for (int i = 0; i < 4; i++)
#pragma unroll
                for (int j = 0; j < 4; j++)
                    acc[i][j] += hv[i] * wv[j];
        }
    }

#pragma unroll
    for (int j = 0; j < 4; j++) {
        int a = a0 + threadIdx.x + 16 * j;
        float bj = b[a];
#pragma unroll
        for (int i = 0; i < 4; i++) {
            int m = m0 + threadIdx.y + 16 * i;
            xout[m * ATTN + a] = acc[i][j] + bj;
        }
    }
}

// ---------------------------------------------------------------------------
// Kernel B: alpha[m][n] = sum_a w[a] * tanh(x1[m][a] + x2[n][a]),
// accumulated directly into row sums (over n) and col sums (over m).
// Tile 64(m) x 64(n), a-chunk 32, 256 threads, 4x4 per thread. MUFU-bound.
// ---------------------------------------------------------------------------
__global__ __launch_bounds__(256) void alpha_kernel(const float* __restrict__ w)
{
    __shared__ float x1s[32][65];
    __shared__ float x2s[32][65];
    __shared__ float wsm[ATTN];
    __shared__ float rowp[64];
    __shared__ float colp[64];

    const int tid = threadIdx.y * 16 + threadIdx.x;
    const int m0 = blockIdx.y * 64;
    const int n0 = blockIdx.x * 64;

    for (int i = tid; i < ATTN; i += 256) wsm[i] = w[i];
    if (tid < 64) { rowp[tid] = 0.0f; colp[tid] = 0.0f; }

    float acc[4][4];
#pragma unroll
    for (int i = 0; i < 4; i++)
#pragma unroll
        for (int j = 0; j < 4; j++) acc[i][j] = 0.0f;

    for (int a0 = 0; a0 < ATTN; a0 += 32) {
        __syncthreads();
#pragma unroll
        for (int it = 0; it < 8; it++) {
            int idx = tid + it * 256;
            int r = idx >> 5;
            int c = idx & 31;
            x1s[c][r] = g_x1[(m0 + r) * ATTN + a0 + c];
            x2s[c][r] = g_x2[(n0 + r) * ATTN + a0 + c];
        }
        __syncthreads();
#pragma unroll 4
        for (int a = 0; a < 32; a++) {
            float wa = wsm[a0 + a];
            float v1[4], v2[4];
#pragma unroll
            for (int i = 0; i < 4; i++) v1[i] = x1s[a][threadIdx.y + 16 * i];
#pragma unroll
            for (int j = 0; j < 4; j++) v2[j] = x2s[a][threadIdx.x + 16 * j];
#pragma unroll
            for (int i = 0; i < 4; i++)
#pragma unroll
                for (int j = 0; j < 4; j++)
                    acc[i][j] += wa * tanh_fast(v1[i] + v2[j]);
        }
    }

    __syncthreads();
    // Per-thread partial reductions into shared, then one global atomic each.
#pragma unroll
    for (int i = 0; i < 4; i++) {
        float r = acc[i][0] + acc[i][1] + acc[i][2] + acc[i][3];
        atomicAdd(&rowp[threadIdx.y + 16 * i], r);
    }
#pragma unroll
    for (int j = 0; j < 4; j++) {
        float c = acc[0][j] + acc[1][j] + acc[2][j] + acc[3][j];
        atomicAdd(&colp[threadIdx.x + 16 * j], c);
    }
    __syncthreads();
    if (tid < 64) {
        atomicAdd(&g_rowsum[m0 + tid], rowp[tid]);
    } else if (tid < 128) {
        atomicAdd(&g_colsum[n0 + tid - 64], colp[tid - 64]);
    }
}

// ---------------------------------------------------------------------------
// Kernel C: softmax over row/col means, then s1 = x1^T p1, s2 = x2^T p2.
// Single block, 512 threads.
// ---------------------------------------------------------------------------
__global__ __launch_bounds__(512) void finalize_kernel(float* __restrict__ out)
{
    __shared__ float e1[M1];
    __shared__ float e2[M2];
    __shared__ float red[512];

    const int tid = threadIdx.x;

    // ---- softmax over rowsum / M2 ----
    float lmax = -1e30f;
    for (int i = tid; i < M1; i += 512) {
        float v = g_rowsum[i] * (1.0f / (float)M2);
        e1[i] = v;
        lmax = fmaxf(lmax, v);
    }
    red[tid] = lmax;
    __syncthreads();
    for (int s = 256; s > 0; s >>= 1) {
        if (tid < s) red[tid] = fmaxf(red[tid], red[tid + s]);
        __syncthreads();
    }
    float mx1 = red[0];
    __syncthreads();
    float lsum = 0.0f;
    for (int i = tid; i < M1; i += 512) {
        float e = __expf(e1[i] - mx1);
        e1[i] = e;
        lsum += e;
    }
    red[tid] = lsum;
    __syncthreads();
    for (int s = 256; s > 0; s >>= 1) {
        if (tid < s) red[tid] += red[tid + s];
        __syncthreads();
    }
    float inv_sum1 = 1.0f / red[0];
    __syncthreads();

    // ---- softmax over colsum / M1 ----
    lmax = -1e30f;
    for (int i = tid; i < M2; i += 512) {
        float v = g_colsum[i] * (1.0f / (float)M1);
        e2[i] = v;
        lmax = fmaxf(lmax, v);
    }
    red[tid] = lmax;
    __syncthreads();
    for (int s = 256; s > 0; s >>= 1) {
        if (tid < s) red[tid] = fmaxf(red[tid], red[tid + s]);
        __syncthreads();
    }
    float mx2 = red[0];
    __syncthreads();
    lsum = 0.0f;
    for (int i = tid; i < M2; i += 512) {
        float e = __expf(e2[i] - mx2);
        e2[i] = e;
        lsum += e;
    }
    red[tid] = lsum;
    __syncthreads();
    for (int s = 256; s > 0; s >>= 1) {
        if (tid < s) red[tid] += red[tid + s];
        __syncthreads();
    }
    float inv_sum2 = 1.0f / red[0];
    __syncthreads();

    // ---- s1 / s2 (weights e* are unnormalized; fold 1/sum in at the end) ----
    if (tid < ATTN) {
        const int a = tid;
        float s0 = 0.0f, s1 = 0.0f, s2 = 0.0f, s3 = 0.0f;
        for (int m = 0; m < M1; m += 4) {
            s0 += g_x1[(m + 0) * ATTN + a] * e1[m + 0];
            s1 += g_x1[(m + 1) * ATTN + a] * e1[m + 1];
            s2 += g_x1[(m + 2) * ATTN + a] * e1[m + 2];
            s3 += g_x1[(m + 3) * ATTN + a] * e1[m + 3];
        }
        out[a] = (s0 + s1 + s2 + s3) * inv_sum1;
    } else {
        const int a = tid - ATTN;
        float s0 = 0.0f, s1 = 0.0f, s2 = 0.0f, s3 = 0.0f;
        for (int m = 0; m < M2; m += 4) {
            s0 += g_x2[(m + 0) * ATTN + a] * e2[m + 0];
            s1 += g_x2[(m + 1) * ATTN + a] * e2[m + 1];
            s2 += g_x2[(m + 2) * ATTN + a] * e2[m + 2];
            s3 += g_x2[(m + 3) * ATTN + a] * e2[m + 3];
        }
        out[ATTN + a] = (s0 + s1 + s2 + s3) * inv_sum2;
    }
}

extern "C" void kernel_launch(void* const* d_in, const int* in_sizes, int n_in,
                              void* d_out, int out_size)
{
    const float* h1 = (const float*)d_in[0];
    const float* h2 = (const float*)d_in[1];
    const float* W1 = (const float*)d_in[2];
    const float* b1 = (const float*)d_in[3];
    const float* W2 = (const float*)d_in[4];
    const float* b2 = (const float*)d_in[5];
    const float* w  = (const float*)d_in[6];
    float* out = (float*)d_out;

    dim3 bt(16, 16);
    proj_kernel<<<dim3(ATTN / 64, M1 / 64, 2), bt>>>(h1, W1, b1, h2, W2, b2);
    alpha_kernel<<<dim3(M2 / 64, M1 / 64), bt>>>(w);
    finalize_kernel<<<1, 512>>>(out);
}

// round 5
// speedup vs baseline: 1.2349x; 1.2349x over previous
#include <cuda_runtime.h>
#include <cuda_bf16.h>
#include <cstdint>

#define M1 768
#define M2 768
#define HID 1024
#define ATTN 256

// ---------------- scratch (no cudaMalloc allowed) ----------------
__device__ float g_x1[M1 * ATTN];
__device__ float g_x2[M2 * ATTN];
__device__ float g_rowsum[M1];
__device__ float g_colsum[M2];
__device__ __align__(16) __nv_bfloat16 g_h_hi[2][M1 * HID];
__device__ __align__(16) __nv_bfloat16 g_h_lo[2][M1 * HID];
__device__ __align__(16) __nv_bfloat16 g_w_hi[2][ATTN * HID];
__device__ __align__(16) __nv_bfloat16 g_w_lo[2][ATTN * HID];

// ---------------- helpers ----------------
__device__ __forceinline__ uint32_t smem_to_u32(const void* p) {
    uint32_t a;
    asm("{ .reg .u64 t; cvta.to.shared.u64 t, %1; cvt.u32.u64 %0, t; }" : "=r"(a) : "l"(p));
    return a;
}
__device__ __forceinline__ float tanh_fast(float x) {
    float r;
    asm("tanh.approx.f32 %0, %1;" : "=f"(r) : "f"(x));
    return r;
}

#define CP_ASYNC_16(dst, src) \
    asm volatile("cp.async.cg.shared.global [%0], [%1], 16;" :: "r"(dst), "l"(src) : "memory")
#define CP_ASYNC_COMMIT() asm volatile("cp.async.commit_group;" ::: "memory")
#define CP_ASYNC_WAIT(n)  asm volatile("cp.async.wait_group %0;" :: "n"(n) : "memory")

#define LDSM_X4(r0, r1, r2, r3, addr) \
    asm volatile("ldmatrix.sync.aligned.m8n8.x4.shared.b16 {%0,%1,%2,%3}, [%4];" \
                 : "=r"(r0), "=r"(r1), "=r"(r2), "=r"(r3) : "r"(addr))
// B tile is [n][k] with k contiguous (== col-major B for mma row.col):
// NON-transposed ldmatrix yields exactly the mma B fragment mapping.
#define LDSM_X2(r0, r1, addr) \
    asm volatile("ldmatrix.sync.aligned.m8n8.x2.shared.b16 {%0,%1}, [%2];" \
                 : "=r"(r0), "=r"(r1) : "r"(addr))

#define MMA_16816(d0, d1, d2, d3, a0, a1, a2, a3, b0, b1) \
    asm volatile("mma.sync.aligned.m16n8k16.row.col.f32.bf16.bf16.f32 " \
                 "{%0,%1,%2,%3}, {%4,%5,%6,%7}, {%8,%9}, {%0,%1,%2,%3};" \
                 : "+f"(d0), "+f"(d1), "+f"(d2), "+f"(d3) \
                 : "r"(a0), "r"(a1), "r"(a2), "r"(a3), "r"(b0), "r"(b1))

// ---------------------------------------------------------------------------
// Kernel 0: fp32 -> bf16 hi/lo split for h1,h2,W1,W2; zero reduction scratch.
// ---------------------------------------------------------------------------
__global__ __launch_bounds__(512) void convert_kernel(
    const float* __restrict__ h1, const float* __restrict__ h2,
    const float* __restrict__ W1, const float* __restrict__ W2)
{
    if (blockIdx.x == 0) {
        for (int j = threadIdx.x; j < M1; j += blockDim.x) { g_rowsum[j] = 0.0f; g_colsum[j] = 0.0f; }
    }
    const int i = blockIdx.x * blockDim.x + threadIdx.x;   // 0 .. 786431
    {
        float x = h1[i];
        __nv_bfloat16 hi = __float2bfloat16(x);
        g_h_hi[0][i] = hi;
        g_h_lo[0][i] = __float2bfloat16(x - __bfloat162float(hi));
        x = h2[i];
        hi = __float2bfloat16(x);
        g_h_hi[1][i] = hi;
        g_h_lo[1][i] = __float2bfloat16(x - __bfloat162float(hi));
    }
    if (i < ATTN * HID) {
        float x = W1[i];
        __nv_bfloat16 hi = __float2bfloat16(x);
        g_w_hi[0][i] = hi;
        g_w_lo[0][i] = __float2bfloat16(x - __bfloat162float(hi));
        x = W2[i];
        hi = __float2bfloat16(x);
        g_w_hi[1][i] = hi;
        g_w_lo[1][i] = __float2bfloat16(x - __bfloat162float(hi));
    }
}

// ---------------------------------------------------------------------------
// Kernel 1: bf16 mma.sync GEMM with 3-term hi/lo compensation.
// x[m][a] = sum_k h[m][k] W[a][k] + bias[a]
// Block tile 128(m) x 64(n), K-chunk 64, 8 warps @ 32x32, cp.async dbl-buf.
// grid = (ATTN/64=4, M/128=6, 2), 256 threads.
// ---------------------------------------------------------------------------
#define AROW 144                  // bytes per smem row (64 bf16 + 16B pad)
#define SZ_A (128 * AROW)         // 18432
#define SZ_B (64 * AROW)          // 9216
#define BUF_SZ (2 * SZ_A + 2 * SZ_B)   // 55296
#define GEMM_SMEM_BYTES (2 * BUF_SZ + 16)

__global__ __launch_bounds__(256) void gemm_kernel(
    const float* __restrict__ bias1, const float* __restrict__ bias2)
{
    extern __shared__ char dsm[];
    const uint32_t smem = smem_to_u32(dsm);

    const int tid  = threadIdx.x;
    const int lane = tid & 31;
    const int wid  = tid >> 5;
    const int wm   = wid & 3;     // 0..3 over M (4 * 32 = 128)
    const int wn   = wid >> 2;    // 0..1 over N (2 * 32 = 64)

    const int z  = blockIdx.z;
    const int m0 = blockIdx.y * 128;
    const int a0 = blockIdx.x * 64;

    const __nv_bfloat16* __restrict__ Ahg = g_h_hi[z];
    const __nv_bfloat16* __restrict__ Alg = g_h_lo[z];
    const __nv_bfloat16* __restrict__ Bhg = g_w_hi[z];
    const __nv_bfloat16* __restrict__ Blg = g_w_lo[z];
    const float* __restrict__ bias = z ? bias2 : bias1;
    float* __restrict__ xout = z ? g_x2 : g_x1;

    // smem offsets per buffer: Ah | Al | Bh | Bl
    auto load_chunk = [&](int c) {
        const int k0 = c * 64;
        const uint32_t buf = smem + (c & 1) * BUF_SZ;
#pragma unroll
        for (int it = 0; it < 4; it++) {
            const int s = tid + it * 256;        // 0..1023
            const int r = s >> 3, cc = s & 7;
            const uint32_t so = r * AROW + cc * 16;
            const __nv_bfloat16* gp = Ahg + (m0 + r) * HID + k0 + cc * 8;
            CP_ASYNC_16(buf + so, gp);
            const __nv_bfloat16* gp2 = Alg + (m0 + r) * HID + k0 + cc * 8;
            CP_ASYNC_16(buf + SZ_A + so, gp2);
        }
#pragma unroll
        for (int it = 0; it < 2; it++) {
            const int s = tid + it * 256;        // 0..511
            const int r = s >> 3, cc = s & 7;
            const uint32_t so = r * AROW + cc * 16;
            const __nv_bfloat16* gp = Bhg + (a0 + r) * HID + k0 + cc * 8;
            CP_ASYNC_16(buf + 2 * SZ_A + so, gp);
            const __nv_bfloat16* gp2 = Blg + (a0 + r) * HID + k0 + cc * 8;
            CP_ASYNC_16(buf + 2 * SZ_A + SZ_B + so, gp2);
        }
        CP_ASYNC_COMMIT();
    };

    float acc[2][4][4];
#pragma unroll
    for (int mi = 0; mi < 2; mi++)
#pragma unroll
        for (int ni = 0; ni < 4; ni++)
#pragma unroll
            for (int q = 0; q < 4; q++) acc[mi][ni][q] = 0.0f;

    // per-lane static address components
    const uint32_t a_lane_off = (wm * 32 + (lane & 15)) * AROW + ((lane >> 4) * 16);
    const uint32_t b_lane_off = (wn * 32 + (lane & 7)) * AROW + (((lane >> 3) & 1) * 16);

    load_chunk(0);

    for (int c = 0; c < 16; c++) {
        if (c + 1 < 16) {
            load_chunk(c + 1);
            CP_ASYNC_WAIT(1);
        } else {
            CP_ASYNC_WAIT(0);
        }
        __syncthreads();

        const uint32_t buf = smem + (c & 1) * BUF_SZ;
        const uint32_t sAh = buf + a_lane_off;
        const uint32_t sAl = buf + SZ_A + a_lane_off;
        const uint32_t sBh = buf + 2 * SZ_A + b_lane_off;
        const uint32_t sBl = buf + 2 * SZ_A + SZ_B + b_lane_off;

#pragma unroll
        for (int ks = 0; ks < 4; ks++) {
            const uint32_t kb = ks * 32;
            uint32_t ah[2][4], al[2][4], bh[4][2], bl[4][2];
#pragma unroll
            for (int mi = 0; mi < 2; mi++) {
                LDSM_X4(ah[mi][0], ah[mi][1], ah[mi][2], ah[mi][3], sAh + mi * (16 * AROW) + kb);
                LDSM_X4(al[mi][0], al[mi][1], al[mi][2], al[mi][3], sAl + mi * (16 * AROW) + kb);
            }
#pragma unroll
            for (int ni = 0; ni < 4; ni++) {
                LDSM_X2(bh[ni][0], bh[ni][1], sBh + ni * (8 * AROW) + kb);
                LDSM_X2(bl[ni][0], bl[ni][1], sBl + ni * (8 * AROW) + kb);
            }
#pragma unroll
            for (int mi = 0; mi < 2; mi++)
#pragma unroll
                for (int ni = 0; ni < 4; ni++) {
                    MMA_16816(acc[mi][ni][0], acc[mi][ni][1], acc[mi][ni][2], acc[mi][ni][3],
                              ah[mi][0], ah[mi][1], ah[mi][2], ah[mi][3], bh[ni][0], bh[ni][1]);
                    MMA_16816(acc[mi][ni][0], acc[mi][ni][1], acc[mi][ni][2], acc[mi][ni][3],
                              ah[mi][0], ah[mi][1], ah[mi][2], ah[mi][3], bl[ni][0], bl[ni][1]);
                    MMA_16816(acc[mi][ni][0], acc[mi][ni][1], acc[mi][ni][2], acc[mi][ni][3],
                              al[mi][0], al[mi][1], al[mi][2], al[mi][3], bh[ni][0], bh[ni][1]);
                }
        }
        __syncthreads();
    }

    // writeback: mma m16n8 acc layout: c0,c1 @ (row=lane>>2, col=2*(lane&3));
    // c2,c3 @ (row+8, same cols)
#pragma unroll
    for (int mi = 0; mi < 2; mi++) {
        const int row = m0 + wm * 32 + mi * 16 + (lane >> 2);
#pragma unroll
        for (int ni = 0; ni < 4; ni++) {
            const int col = a0 + wn * 32 + ni * 8 + (lane & 3) * 2;
            xout[row * ATTN + col]           = acc[mi][ni][0] + bias[col];
            xout[row * ATTN + col + 1]       = acc[mi][ni][1] + bias[col + 1];
            xout[(row + 8) * ATTN + col]     = acc[mi][ni][2] + bias[col];
            xout[(row + 8) * ATTN + col + 1] = acc[mi][ni][3] + bias[col + 1];
        }
    }
}

// ---------------------------------------------------------------------------
// Kernel 2: alpha row/col sums with tanh (MUFU-bound; near floor already).
// ---------------------------------------------------------------------------
__global__ __launch_bounds__(256) void alpha_kernel(const float* __restrict__ w)
{
    __shared__ float x1s[32][65];
    __shared__ float x2s[32][65];
    __shared__ float wsm[ATTN];
    __shared__ float rowp[64];
    __shared__ float colp[64];

    const int tid = threadIdx.y * 16 + threadIdx.x;
    const int m0 = blockIdx.y * 64;
    const int n0 = blockIdx.x * 64;

    for (int i = tid; i < ATTN; i += 256) wsm[i] = w[i];
    if (tid < 64) { rowp[tid] = 0.0f; colp[tid] = 0.0f; }

    float acc[4][4];
#pragma unroll
    for (int i = 0; i < 4; i++)
#pragma unroll
        for (int j = 0; j < 4; j++) acc[i][j] = 0.0f;

    for (int a0 = 0; a0 < ATTN; a0 += 32) {
        __syncthreads();
#pragma unroll
        for (int it = 0; it < 8; it++) {
            int idx = tid + it * 256;
            int r = idx >> 5;
            int c = idx & 31;
            x1s[c][r] = g_x1[(m0 + r) * ATTN + a0 + c];
            x2s[c][r] = g_x2[(n0 + r) * ATTN + a0 + c];
        }
        __syncthreads();
#pragma unroll 4
        for (int a = 0; a < 32; a++) {
            float wa = wsm[a0 + a];
            float v1[4], v2[4];
#pragma unroll
            for (int i = 0; i < 4; i++) v1[i] = x1s[a][threadIdx.y + 16 * i];
#pragma unroll
            for (int j = 0; j < 4; j++) v2[j] = x2s[a][threadIdx.x + 16 * j];
#pragma unroll
            for (int i = 0; i < 4; i++)
#pragma unroll
                for (int j = 0; j < 4; j++)
                    acc[i][j] += wa * tanh_fast(v1[i] + v2[j]);
        }
    }

    __syncthreads();
#pragma unroll
    for (int i = 0; i < 4; i++) {
        float r = acc[i][0] + acc[i][1] + acc[i][2] + acc[i][3];
        atomicAdd(&rowp[threadIdx.y + 16 * i], r);
    }
#pragma unroll
    for (int j = 0; j < 4; j++) {
        float c = acc[0][j] + acc[1][j] + acc[2][j] + acc[3][j];
        atomicAdd(&colp[threadIdx.x + 16 * j], c);
    }
    __syncthreads();
    if (tid < 64) {
        atomicAdd(&g_rowsum[m0 + tid], rowp[tid]);
    } else if (tid < 128) {
        atomicAdd(&g_colsum[n0 + tid - 64], colp[tid - 64]);
    }
}

// ---------------------------------------------------------------------------
// Kernel 3: dual softmax + weighted reductions -> out[1, 512].
// ---------------------------------------------------------------------------
__global__ __launch_bounds__(512) void finalize_kernel(float* __restrict__ out)
{
    __shared__ float e1[M1];
    __shared__ float e2[M2];
    __shared__ float red[512];

    const int tid = threadIdx.x;

    float lmax = -1e30f;
    for (int i = tid; i < M1; i += 512) {
        float v = g_rowsum[i] * (1.0f / (float)M2);
        e1[i] = v;
        lmax = fmaxf(lmax, v);
    }
    red[tid] = lmax;
    __syncthreads();
    for (int s = 256; s > 0; s >>= 1) {
        if (tid < s) red[tid] = fmaxf(red[tid], red[tid + s]);
        __syncthreads();
    }
    float mx1 = red[0];
    __syncthreads();
    float lsum = 0.0f;
    for (int i = tid; i < M1; i += 512) {
        float e = __expf(e1[i] - mx1);
        e1[i] = e;
        lsum += e;
    }
    red[tid] = lsum;
    __syncthreads();
    for (int s = 256; s > 0; s >>= 1) {
        if (tid < s) red[tid] += red[tid + s];
        __syncthreads();
    }
    float inv_sum1 = 1.0f / red[0];
    __syncthreads();

    lmax = -1e30f;
    for (int i = tid; i < M2; i += 512) {
        float v = g_colsum[i] * (1.0f / (float)M1);
        e2[i] = v;
        lmax = fmaxf(lmax, v);
    }
    red[tid] = lmax;
    __syncthreads();
    for (int s = 256; s > 0; s >>= 1) {
        if (tid < s) red[tid] = fmaxf(red[tid], red[tid + s]);
        __syncthreads();
    }
    float mx2 = red[0];
    __syncthreads();
    lsum = 0.0f;
    for (int i = tid; i < M2; i += 512) {
        float e = __expf(e2[i] - mx2);
        e2[i] = e;
        lsum += e;
    }
    red[tid] = lsum;
    __syncthreads();
    for (int s = 256; s > 0; s >>= 1) {
        if (tid < s) red[tid] += red[tid + s];
        __syncthreads();
    }
    float inv_sum2 = 1.0f / red[0];
    __syncthreads();

    if (tid < ATTN) {
        const int a = tid;
        float s0 = 0.0f, s1 = 0.0f, s2 = 0.0f, s3 = 0.0f;
        for (int m = 0; m < M1; m += 4) {
            s0 += g_x1[(m + 0) * ATTN + a] * e1[m + 0];
            s1 += g_x1[(m + 1) * ATTN + a] * e1[m + 1];
            s2 += g_x1[(m + 2) * ATTN + a] * e1[m + 2];
            s3 += g_x1[(m + 3) * ATTN + a] * e1[m + 3];
        }
        out[a] = (s0 + s1 + s2 + s3) * inv_sum1;
    } else {
        const int a = tid - ATTN;
        float s0 = 0.0f, s1 = 0.0f, s2 = 0.0f, s3 = 0.0f;
        for (int m = 0; m < M2; m += 4) {
            s0 += g_x2[(m + 0) * ATTN + a] * e2[m + 0];
            s1 += g_x2[(m + 1) * ATTN + a] * e2[m + 1];
            s2 += g_x2[(m + 2) * ATTN + a] * e2[m + 2];
            s3 += g_x2[(m + 3) * ATTN + a] * e2[m + 3];
        }
        out[ATTN + a] = (s0 + s1 + s2 + s3) * inv_sum2;
    }
}

extern "C" void kernel_launch(void* const* d_in, const int* in_sizes, int n_in,
                              void* d_out, int out_size)
{
    const float* h1 = (const float*)d_in[0];
    const float* h2 = (const float*)d_in[1];
    const float* W1 = (const float*)d_in[2];
    const float* b1 = (const float*)d_in[3];
    const float* W2 = (const float*)d_in[4];
    const float* b2 = (const float*)d_in[5];
    const float* w  = (const float*)d_in[6];
    float* out = (float*)d_out;

    cudaFuncSetAttribute(gemm_kernel, cudaFuncAttributeMaxDynamicSharedMemorySize, GEMM_SMEM_BYTES);

    convert_kernel<<<1536, 512>>>(h1, h2, W1, W2);
    gemm_kernel<<<dim3(ATTN / 64, M1 / 128, 2), 256, GEMM_SMEM_BYTES>>>(b1, b2);
    alpha_kernel<<<dim3(M2 / 64, M1 / 64), dim3(16, 16)>>>(w);
    finalize_kernel<<<1, 512>>>(out);
}

// round 7
// speedup vs baseline: 1.4687x; 1.1893x over previous
#include <cuda_runtime.h>
#include <cuda_bf16.h>
#include <cstdint>

#define M1 768
#define M2 768
#define HID 1024
#define ATTN 256

// ---------------- scratch (no cudaMalloc allowed) ----------------
__device__ float g_x1[M1 * ATTN];
__device__ float g_x2[M2 * ATTN];
__device__ float g_rowsum[M1];
__device__ float g_colsum[M2];
__device__ float g_p1[M1];
__device__ float g_p2[M2];
__device__ __align__(16) __nv_bfloat16 g_h_hi[2][M1 * HID];
__device__ __align__(16) __nv_bfloat16 g_h_lo[2][M1 * HID];
__device__ __align__(16) __nv_bfloat16 g_w_hi[2][ATTN * HID];
__device__ __align__(16) __nv_bfloat16 g_w_lo[2][ATTN * HID];

// ---------------- helpers ----------------
__device__ __forceinline__ uint32_t smem_to_u32(const void* p) {
    uint32_t a;
    asm("{ .reg .u64 t; cvta.to.shared.u64 t, %1; cvt.u32.u64 %0, t; }" : "=r"(a) : "l"(p));
    return a;
}
__device__ __forceinline__ float tanh_fast(float x) {
    float r;
    asm("tanh.approx.f32 %0, %1;" : "=f"(r) : "f"(x));
    return r;
}

#define CP_ASYNC_16(dst, src) \
    asm volatile("cp.async.cg.shared.global [%0], [%1], 16;" :: "r"(dst), "l"(src) : "memory")
#define CP_ASYNC_COMMIT() asm volatile("cp.async.commit_group;" ::: "memory")
#define CP_ASYNC_WAIT(n)  asm volatile("cp.async.wait_group %0;" :: "n"(n) : "memory")

#define LDSM_X4(r0, r1, r2, r3, addr) \
    asm volatile("ldmatrix.sync.aligned.m8n8.x4.shared.b16 {%0,%1,%2,%3}, [%4];" \
                 : "=r"(r0), "=r"(r1), "=r"(r2), "=r"(r3) : "r"(addr))
// B tile is [n][k] with k contiguous (== col-major B for mma row.col):
// NON-transposed ldmatrix yields exactly the mma B fragment mapping.
#define LDSM_X2(r0, r1, addr) \
    asm volatile("ldmatrix.sync.aligned.m8n8.x2.shared.b16 {%0,%1}, [%2];" \
                 : "=r"(r0), "=r"(r1) : "r"(addr))

#define MMA_16816(d0, d1, d2, d3, a0, a1, a2, a3, b0, b1) \
    asm volatile("mma.sync.aligned.m16n8k16.row.col.f32.bf16.bf16.f32 " \
                 "{%0,%1,%2,%3}, {%4,%5,%6,%7}, {%8,%9}, {%0,%1,%2,%3};" \
                 : "+f"(d0), "+f"(d1), "+f"(d2), "+f"(d3) \
                 : "r"(a0), "r"(a1), "r"(a2), "r"(a3), "r"(b0), "r"(b1))

// ---------------------------------------------------------------------------
// Kernel 0: fp32 -> bf16 hi/lo split for h1,h2,W1,W2; zero reduction scratch.
// ---------------------------------------------------------------------------
__global__ __launch_bounds__(512) void convert_kernel(
    const float* __restrict__ h1, const float* __restrict__ h2,
    const float* __restrict__ W1, const float* __restrict__ W2)
{
    if (blockIdx.x == 0) {
        for (int j = threadIdx.x; j < M1; j += blockDim.x) { g_rowsum[j] = 0.0f; g_colsum[j] = 0.0f; }
    }
    const int i = blockIdx.x * blockDim.x + threadIdx.x;   // 0 .. 786431
    {
        float x = h1[i];
        __nv_bfloat16 hi = __float2bfloat16(x);
        g_h_hi[0][i] = hi;
        g_h_lo[0][i] = __float2bfloat16(x - __bfloat162float(hi));
        x = h2[i];
        hi = __float2bfloat16(x);
        g_h_hi[1][i] = hi;
        g_h_lo[1][i] = __float2bfloat16(x - __bfloat162float(hi));
    }
    if (i < ATTN * HID) {
        float x = W1[i];
        __nv_bfloat16 hi = __float2bfloat16(x);
        g_w_hi[0][i] = hi;
        g_w_lo[0][i] = __float2bfloat16(x - __bfloat162float(hi));
        x = W2[i];
        hi = __float2bfloat16(x);
        g_w_hi[1][i] = hi;
        g_w_lo[1][i] = __float2bfloat16(x - __bfloat162float(hi));
    }
}

// ---------------------------------------------------------------------------
// Kernel 1: bf16 mma.sync GEMM with 3-term hi/lo compensation.
// ---------------------------------------------------------------------------
#define AROW 144                  // bytes per smem row (64 bf16 + 16B pad)
#define SZ_A (128 * AROW)         // 18432
#define SZ_B (64 * AROW)          // 9216
#define BUF_SZ (2 * SZ_A + 2 * SZ_B)   // 55296
#define GEMM_SMEM_BYTES (2 * BUF_SZ + 16)

__global__ __launch_bounds__(256) void gemm_kernel(
    const float* __restrict__ bias1, const float* __restrict__ bias2)
{
    extern __shared__ char dsm[];
    const uint32_t smem = smem_to_u32(dsm);

    const int tid  = threadIdx.x;
    const int lane = tid & 31;
    const int wid  = tid >> 5;
    const int wm   = wid & 3;     // 0..3 over M (4 * 32 = 128)
    const int wn   = wid >> 2;    // 0..1 over N (2 * 32 = 64)

    const int z  = blockIdx.z;
    const int m0 = blockIdx.y * 128;
    const int a0 = blockIdx.x * 64;

    const __nv_bfloat16* __restrict__ Ahg = g_h_hi[z];
    const __nv_bfloat16* __restrict__ Alg = g_h_lo[z];
    const __nv_bfloat16* __restrict__ Bhg = g_w_hi[z];
    const __nv_bfloat16* __restrict__ Blg = g_w_lo[z];
    const float* __restrict__ bias = z ? bias2 : bias1;
    float* __restrict__ xout = z ? g_x2 : g_x1;

    auto load_chunk = [&](int c) {
        const int k0 = c * 64;
        const uint32_t buf = smem + (c & 1) * BUF_SZ;
#pragma unroll
        for (int it = 0; it < 4; it++) {
            const int s = tid + it * 256;        // 0..1023
            const int r = s >> 3, cc = s & 7;
            const uint32_t so = r * AROW + cc * 16;
            CP_ASYNC_16(buf + so, Ahg + (m0 + r) * HID + k0 + cc * 8);
            CP_ASYNC_16(buf + SZ_A + so, Alg + (m0 + r) * HID + k0 + cc * 8);
        }
#pragma unroll
        for (int it = 0; it < 2; it++) {
            const int s = tid + it * 256;        // 0..511
            const int r = s >> 3, cc = s & 7;
            const uint32_t so = r * AROW + cc * 16;
            CP_ASYNC_16(buf + 2 * SZ_A + so, Bhg + (a0 + r) * HID + k0 + cc * 8);
            CP_ASYNC_16(buf + 2 * SZ_A + SZ_B + so, Blg + (a0 + r) * HID + k0 + cc * 8);
        }
        CP_ASYNC_COMMIT();
    };

    float acc[2][4][4];
#pragma unroll
    for (int mi = 0; mi < 2; mi++)
#pragma unroll
        for (int ni = 0; ni < 4; ni++)
#pragma unroll
            for (int q = 0; q < 4; q++) acc[mi][ni][q] = 0.0f;

    const uint32_t a_lane_off = (wm * 32 + (lane & 15)) * AROW + ((lane >> 4) * 16);
    const uint32_t b_lane_off = (wn * 32 + (lane & 7)) * AROW + (((lane >> 3) & 1) * 16);

    load_chunk(0);

    for (int c = 0; c < 16; c++) {
        if (c + 1 < 16) {
            load_chunk(c + 1);
            CP_ASYNC_WAIT(1);
        } else {
            CP_ASYNC_WAIT(0);
        }
        __syncthreads();

        const uint32_t buf = smem + (c & 1) * BUF_SZ;
        const uint32_t sAh = buf + a_lane_off;
        const uint32_t sAl = buf + SZ_A + a_lane_off;
        const uint32_t sBh = buf + 2 * SZ_A + b_lane_off;
        const uint32_t sBl = buf + 2 * SZ_A + SZ_B + b_lane_off;

#pragma unroll
        for (int ks = 0; ks < 4; ks++) {
            const uint32_t kb = ks * 32;
            uint32_t ah[2][4], al[2][4], bh[4][2], bl[4][2];
#pragma unroll
            for (int mi = 0; mi < 2; mi++) {
                LDSM_X4(ah[mi][0], ah[mi][1], ah[mi][2], ah[mi][3], sAh + mi * (16 * AROW) + kb);
                LDSM_X4(al[mi][0], al[mi][1], al[mi][2], al[mi][3], sAl + mi * (16 * AROW) + kb);
            }
#pragma unroll
            for (int ni = 0; ni < 4; ni++) {
                LDSM_X2(bh[ni][0], bh[ni][1], sBh + ni * (8 * AROW) + kb);
                LDSM_X2(bl[ni][0], bl[ni][1], sBl + ni * (8 * AROW) + kb);
            }
#pragma unroll
            for (int mi = 0; mi < 2; mi++)
#pragma unroll
                for (int ni = 0; ni < 4; ni++) {
                    MMA_16816(acc[mi][ni][0], acc[mi][ni][1], acc[mi][ni][2], acc[mi][ni][3],
                              ah[mi][0], ah[mi][1], ah[mi][2], ah[mi][3], bh[ni][0], bh[ni][1]);
                    MMA_16816(acc[mi][ni][0], acc[mi][ni][1], acc[mi][ni][2], acc[mi][ni][3],
                              ah[mi][0], ah[mi][1], ah[mi][2], ah[mi][3], bl[ni][0], bl[ni][1]);
                    MMA_16816(acc[mi][ni][0], acc[mi][ni][1], acc[mi][ni][2], acc[mi][ni][3],
                              al[mi][0], al[mi][1], al[mi][2], al[mi][3], bh[ni][0], bh[ni][1]);
                }
        }
        __syncthreads();
    }

#pragma unroll
    for (int mi = 0; mi < 2; mi++) {
        const int row = m0 + wm * 32 + mi * 16 + (lane >> 2);
#pragma unroll
        for (int ni = 0; ni < 4; ni++) {
            const int col = a0 + wn * 32 + ni * 8 + (lane & 3) * 2;
            xout[row * ATTN + col]           = acc[mi][ni][0] + bias[col];
            xout[row * ATTN + col + 1]       = acc[mi][ni][1] + bias[col + 1];
            xout[(row + 8) * ATTN + col]     = acc[mi][ni][2] + bias[col];
            xout[(row + 8) * ATTN + col + 1] = acc[mi][ni][3] + bias[col + 1];
        }
    }
}

// ---------------------------------------------------------------------------
// Kernel 2: alpha row/col sums with tanh (MUFU-bound; near floor already).
// ---------------------------------------------------------------------------
__global__ __launch_bounds__(256) void alpha_kernel(const float* __restrict__ w)
{
    __shared__ float x1s[32][65];
    __shared__ float x2s[32][65];
    __shared__ float wsm[ATTN];
    __shared__ float rowp[64];
    __shared__ float colp[64];

    const int tid = threadIdx.y * 16 + threadIdx.x;
    const int m0 = blockIdx.y * 64;
    const int n0 = blockIdx.x * 64;

    for (int i = tid; i < ATTN; i += 256) wsm[i] = w[i];
    if (tid < 64) { rowp[tid] = 0.0f; colp[tid] = 0.0f; }

    float acc[4][4];
#pragma unroll
    for (int i = 0; i < 4; i++)
#pragma unroll
        for (int j = 0; j < 4; j++) acc[i][j] = 0.0f;

    for (int a0 = 0; a0 < ATTN; a0 += 32) {
        __syncthreads();
#pragma unroll
        for (int it = 0; it < 8; it++) {
            int idx = tid + it * 256;
            int r = idx >> 5;
            int c = idx & 31;
            x1s[c][r] = g_x1[(m0 + r) * ATTN + a0 + c];
            x2s[c][r] = g_x2[(n0 + r) * ATTN + a0 + c];
        }
        __syncthreads();
#pragma unroll 4
        for (int a = 0; a < 32; a++) {
            float wa = wsm[a0 + a];
            float v1[4], v2[4];
#pragma unroll
            for (int i = 0; i < 4; i++) v1[i] = x1s[a][threadIdx.y + 16 * i];
#pragma unroll
            for (int j = 0; j < 4; j++) v2[j] = x2s[a][threadIdx.x + 16 * j];
#pragma unroll
            for (int i = 0; i < 4; i++)
#pragma unroll
                for (int j = 0; j < 4; j++)
                    acc[i][j] += wa * tanh_fast(v1[i] + v2[j]);
        }
    }

    __syncthreads();
#pragma unroll
    for (int i = 0; i < 4; i++) {
        float r = acc[i][0] + acc[i][1] + acc[i][2] + acc[i][3];
        atomicAdd(&rowp[threadIdx.y + 16 * i], r);
    }
#pragma unroll
    for (int j = 0; j < 4; j++) {
        float c = acc[0][j] + acc[1][j] + acc[2][j] + acc[3][j];
        atomicAdd(&colp[threadIdx.x + 16 * j], c);
    }
    __syncthreads();
    if (tid < 64) {
        atomicAdd(&g_rowsum[m0 + tid], rowp[tid]);
    } else if (tid < 128) {
        atomicAdd(&g_colsum[n0 + tid - 64], colp[tid - 64]);
    }
}

// ---------------------------------------------------------------------------
// Kernel 3a: dual softmax -> normalized probs g_p1/g_p2; zero d_out.
// Single block (cheap: 2x 768 elements).
// ---------------------------------------------------------------------------
__global__ __launch_bounds__(512) void softmax_kernel(float* __restrict__ out)
{
    __shared__ float red[512];
    const int tid = threadIdx.x;

    out[tid] = 0.0f;   // d_out is poisoned; matvec accumulates into it

    // softmax over rowsum/M2 -> g_p1
    float v1 = g_rowsum[tid] * (1.0f / (float)M2);
    float v2 = (tid < M1 - 512) ? g_rowsum[512 + tid] * (1.0f / (float)M2) : -1e30f;
    float lmax = fmaxf(v1, v2);
    red[tid] = lmax;
    __syncthreads();
    for (int s = 256; s > 0; s >>= 1) {
        if (tid < s) red[tid] = fmaxf(red[tid], red[tid + s]);
        __syncthreads();
    }
    float mx = red[0];
    __syncthreads();
    float e1 = __expf(v1 - mx);
    float e2 = (tid < M1 - 512) ? __expf(v2 - mx) : 0.0f;
    red[tid] = e1 + e2;
    __syncthreads();
    for (int s = 256; s > 0; s >>= 1) {
        if (tid < s) red[tid] += red[tid + s];
        __syncthreads();
    }
    float inv = 1.0f / red[0];
    g_p1[tid] = e1 * inv;
    if (tid < M1 - 512) g_p1[512 + tid] = e2 * inv;
    __syncthreads();

    // softmax over colsum/M1 -> g_p2
    v1 = g_colsum[tid] * (1.0f / (float)M1);
    v2 = (tid < M2 - 512) ? g_colsum[512 + tid] * (1.0f / (float)M1) : -1e30f;
    lmax = fmaxf(v1, v2);
    red[tid] = lmax;
    __syncthreads();
    for (int s = 256; s > 0; s >>= 1) {
        if (tid < s) red[tid] = fmaxf(red[tid], red[tid + s]);
        __syncthreads();
    }
    mx = red[0];
    __syncthreads();
    e1 = __expf(v1 - mx);
    e2 = (tid < M2 - 512) ? __expf(v2 - mx) : 0.0f;
    red[tid] = e1 + e2;
    __syncthreads();
    for (int s = 256; s > 0; s >>= 1) {
        if (tid < s) red[tid] += red[tid + s];
        __syncthreads();
    }
    inv = 1.0f / red[0];
    g_p2[tid] = e1 * inv;
    if (tid < M2 - 512) g_p2[512 + tid] = e2 * inv;
}

// ---------------------------------------------------------------------------
// Kernel 3b: s = x^T p, parallel over (tensor, m-chunk). Coalesced rows,
// per-block partial -> one atomicAdd per (block, column) into out.
// grid = (12 m-chunks, 2 tensors), 256 threads (thread = column).
// ---------------------------------------------------------------------------
__global__ __launch_bounds__(256) void matvec_kernel(float* __restrict__ out)
{
    const int z  = blockIdx.y;
    const int m0 = blockIdx.x * 64;
    const int a  = threadIdx.x;
    const float* __restrict__ x = z ? g_x2 : g_x1;
    const float* __restrict__ p = z ? g_p2 : g_p1;

    float s0 = 0.0f, s1 = 0.0f, s2 = 0.0f, s3 = 0.0f;
#pragma unroll 4
    for (int m = 0; m < 64; m += 4) {
        s0 += x[(m0 + m + 0) * ATTN + a] * p[m0 + m + 0];
        s1 += x[(m0 + m + 1) * ATTN + a] * p[m0 + m + 1];
        s2 += x[(m0 + m + 2) * ATTN + a] * p[m0 + m + 2];
        s3 += x[(m0 + m + 3) * ATTN + a] * p[m0 + m + 3];
    }
    atomicAdd(&out[z * ATTN + a], (s0 + s1) + (s2 + s3));
}

extern "C" void kernel_launch(void* const* d_in, const int* in_sizes, int n_in,
                              void* d_out, int out_size)
{
    const float* h1 = (const float*)d_in[0];
    const float* h2 = (const float*)d_in[1];
    const float* W1 = (const float*)d_in[2];
    const float* b1 = (const float*)d_in[3];
    const float* W2 = (const float*)d_in[4];
    const float* b2 = (const float*)d_in[5];
    const float* w  = (const float*)d_in[6];
    float* out = (float*)d_out;

    cudaFuncSetAttribute(gemm_kernel, cudaFuncAttributeMaxDynamicSharedMemorySize, GEMM_SMEM_BYTES);

    convert_kernel<<<1536, 512>>>(h1, h2, W1, W2);
    gemm_kernel<<<dim3(ATTN / 64, M1 / 128, 2), 256, GEMM_SMEM_BYTES>>>(b1, b2);
    alpha_kernel<<<dim3(M2 / 64, M1 / 64), dim3(16, 16)>>>(w);
    softmax_kernel<<<1, 512>>>(out);
    matvec_kernel<<<dim3(M1 / 64, 2), 256>>>(out);
}

// round 8
// speedup vs baseline: 1.7043x; 1.1604x over previous
#include <cuda_runtime.h>
#include <cuda_bf16.h>
#include <cstdint>

#define M1 768
#define M2 768
#define HID 1024
#define ATTN 256

// ---------------- scratch (no cudaMalloc allowed) ----------------
__device__ float g_x1[M1 * ATTN];
__device__ float g_x2[M2 * ATTN];
__device__ float g_rowsum[M1];
__device__ float g_colsum[M2];
__device__ __align__(16) __nv_bfloat16 g_h_hi[2][M1 * HID];
__device__ __align__(16) __nv_bfloat16 g_h_lo[2][M1 * HID];
__device__ __align__(16) __nv_bfloat16 g_w_hi[2][ATTN * HID];
__device__ __align__(16) __nv_bfloat16 g_w_lo[2][ATTN * HID];

// ---------------- helpers ----------------
__device__ __forceinline__ uint32_t smem_to_u32(const void* p) {
    uint32_t a;
    asm("{ .reg .u64 t; cvta.to.shared.u64 t, %1; cvt.u32.u64 %0, t; }" : "=r"(a) : "l"(p));
    return a;
}
__device__ __forceinline__ float tanh_fast(float x) {
    float r;
    asm("tanh.approx.f32 %0, %1;" : "=f"(r) : "f"(x));
    return r;
}

#define CP_ASYNC_16(dst, src) \
    asm volatile("cp.async.cg.shared.global [%0], [%1], 16;" :: "r"(dst), "l"(src) : "memory")
#define CP_ASYNC_COMMIT() asm volatile("cp.async.commit_group;" ::: "memory")
#define CP_ASYNC_WAIT(n)  asm volatile("cp.async.wait_group %0;" :: "n"(n) : "memory")

#define LDSM_X4(r0, r1, r2, r3, addr) \
    asm volatile("ldmatrix.sync.aligned.m8n8.x4.shared.b16 {%0,%1,%2,%3}, [%4];" \
                 : "=r"(r0), "=r"(r1), "=r"(r2), "=r"(r3) : "r"(addr))
// B tile is [n][k] with k contiguous (== col-major B for mma row.col):
// NON-transposed ldmatrix yields exactly the mma B fragment mapping.
#define LDSM_X2(r0, r1, addr) \
    asm volatile("ldmatrix.sync.aligned.m8n8.x2.shared.b16 {%0,%1}, [%2];" \
                 : "=r"(r0), "=r"(r1) : "r"(addr))

#define MMA_16816(d0, d1, d2, d3, a0, a1, a2, a3, b0, b1) \
    asm volatile("mma.sync.aligned.m16n8k16.row.col.f32.bf16.bf16.f32 " \
                 "{%0,%1,%2,%3}, {%4,%5,%6,%7}, {%8,%9}, {%0,%1,%2,%3};" \
                 : "+f"(d0), "+f"(d1), "+f"(d2), "+f"(d3) \
                 : "r"(a0), "r"(a1), "r"(a2), "r"(a3), "r"(b0), "r"(b1))

// ---------------------------------------------------------------------------
// Kernel 0: fp32 -> bf16 hi/lo split; zero reduction scratch and d_out.
// ---------------------------------------------------------------------------
__global__ __launch_bounds__(512) void convert_kernel(
    const float* __restrict__ h1, const float* __restrict__ h2,
    const float* __restrict__ W1, const float* __restrict__ W2,
    float* __restrict__ out)
{
    if (blockIdx.x == 0) {
        for (int j = threadIdx.x; j < M1; j += blockDim.x) { g_rowsum[j] = 0.0f; g_colsum[j] = 0.0f; }
        out[threadIdx.x] = 0.0f;   // out_size == 512, poisoned by harness
    }
    const int i = blockIdx.x * blockDim.x + threadIdx.x;   // 0 .. 786431
    {
        float x = h1[i];
        __nv_bfloat16 hi = __float2bfloat16(x);
        g_h_hi[0][i] = hi;
        g_h_lo[0][i] = __float2bfloat16(x - __bfloat162float(hi));
        x = h2[i];
        hi = __float2bfloat16(x);
        g_h_hi[1][i] = hi;
        g_h_lo[1][i] = __float2bfloat16(x - __bfloat162float(hi));
    }
    if (i < ATTN * HID) {
        float x = W1[i];
        __nv_bfloat16 hi = __float2bfloat16(x);
        g_w_hi[0][i] = hi;
        g_w_lo[0][i] = __float2bfloat16(x - __bfloat162float(hi));
        x = W2[i];
        hi = __float2bfloat16(x);
        g_w_hi[1][i] = hi;
        g_w_lo[1][i] = __float2bfloat16(x - __bfloat162float(hi));
    }
}

// ---------------------------------------------------------------------------
// Kernel 1: bf16 mma.sync GEMM, 3-term hi/lo compensation.
// Block tile 64(m) x 64(n), K-chunk 64, 8 warps @ 16x32, cp.async dbl-buf.
// grid = (4, 12, 2) = 96 CTAs (2x the SM coverage of the 128-row tile).
// ---------------------------------------------------------------------------
#define AROW 144                  // bytes per smem row (64 bf16 + 16B pad)
#define SZ_T (64 * AROW)          // 9216 per tile (Ah/Al/Bh/Bl)
#define BUF_SZ (4 * SZ_T)         // 36864
#define GEMM_SMEM_BYTES (2 * BUF_SZ + 16)

__global__ __launch_bounds__(256) void gemm_kernel(
    const float* __restrict__ bias1, const float* __restrict__ bias2)
{
    extern __shared__ char dsm[];
    const uint32_t smem = smem_to_u32(dsm);

    const int tid  = threadIdx.x;
    const int lane = tid & 31;
    const int wid  = tid >> 5;
    const int wm   = wid & 3;     // 0..3 over M (4 * 16 = 64)
    const int wn   = wid >> 2;    // 0..1 over N (2 * 32 = 64)

    const int z  = blockIdx.z;
    const int m0 = blockIdx.y * 64;
    const int a0 = blockIdx.x * 64;

    const __nv_bfloat16* __restrict__ Ahg = g_h_hi[z];
    const __nv_bfloat16* __restrict__ Alg = g_h_lo[z];
    const __nv_bfloat16* __restrict__ Bhg = g_w_hi[z];
    const __nv_bfloat16* __restrict__ Blg = g_w_lo[z];
    const float* __restrict__ bias = z ? bias2 : bias1;
    float* __restrict__ xout = z ? g_x2 : g_x1;

    auto load_chunk = [&](int c) {
        const int k0 = c * 64;
        const uint32_t buf = smem + (c & 1) * BUF_SZ;
#pragma unroll
        for (int it = 0; it < 2; it++) {
            const int s = tid + it * 256;        // 0..511
            const int r = s >> 3, cc = s & 7;
            const uint32_t so = r * AROW + cc * 16;
            CP_ASYNC_16(buf + so,              Ahg + (m0 + r) * HID + k0 + cc * 8);
            CP_ASYNC_16(buf + SZ_T + so,       Alg + (m0 + r) * HID + k0 + cc * 8);
            CP_ASYNC_16(buf + 2 * SZ_T + so,   Bhg + (a0 + r) * HID + k0 + cc * 8);
            CP_ASYNC_16(buf + 3 * SZ_T + so,   Blg + (a0 + r) * HID + k0 + cc * 8);
        }
        CP_ASYNC_COMMIT();
    };

    float acc[4][4];
#pragma unroll
    for (int ni = 0; ni < 4; ni++)
#pragma unroll
        for (int q = 0; q < 4; q++) acc[ni][q] = 0.0f;

    const uint32_t a_lane_off = (wm * 16 + (lane & 15)) * AROW + ((lane >> 4) * 16);
    const uint32_t b_lane_off = (wn * 32 + (lane & 7)) * AROW + (((lane >> 3) & 1) * 16);

    load_chunk(0);

    for (int c = 0; c < 16; c++) {
        if (c + 1 < 16) {
            load_chunk(c + 1);
            CP_ASYNC_WAIT(1);
        } else {
            CP_ASYNC_WAIT(0);
        }
        __syncthreads();

        const uint32_t buf = smem + (c & 1) * BUF_SZ;
        const uint32_t sAh = buf + a_lane_off;
        const uint32_t sAl = buf + SZ_T + a_lane_off;
        const uint32_t sBh = buf + 2 * SZ_T + b_lane_off;
        const uint32_t sBl = buf + 3 * SZ_T + b_lane_off;

#pragma unroll
        for (int ks = 0; ks < 4; ks++) {
            const uint32_t kb = ks * 32;
            uint32_t ah[4], al[4], bh[4][2], bl[4][2];
            LDSM_X4(ah[0], ah[1], ah[2], ah[3], sAh + kb);
            LDSM_X4(al[0], al[1], al[2], al[3], sAl + kb);
#pragma unroll
            for (int ni = 0; ni < 4; ni++) {
                LDSM_X2(bh[ni][0], bh[ni][1], sBh + ni * (8 * AROW) + kb);
                LDSM_X2(bl[ni][0], bl[ni][1], sBl + ni * (8 * AROW) + kb);
            }
#pragma unroll
            for (int ni = 0; ni < 4; ni++) {
                MMA_16816(acc[ni][0], acc[ni][1], acc[ni][2], acc[ni][3],
                          ah[0], ah[1], ah[2], ah[3], bh[ni][0], bh[ni][1]);
                MMA_16816(acc[ni][0], acc[ni][1], acc[ni][2], acc[ni][3],
                          ah[0], ah[1], ah[2], ah[3], bl[ni][0], bl[ni][1]);
                MMA_16816(acc[ni][0], acc[ni][1], acc[ni][2], acc[ni][3],
                          al[0], al[1], al[2], al[3], bh[ni][0], bh[ni][1]);
            }
        }
        __syncthreads();
    }

    // mma m16n8 acc layout: c0,c1 @ (row=lane>>2, col=2*(lane&3)); c2,c3 @ row+8
    const int row = m0 + wm * 16 + (lane >> 2);
#pragma unroll
    for (int ni = 0; ni < 4; ni++) {
        const int col = a0 + wn * 32 + ni * 8 + (lane & 3) * 2;
        xout[row * ATTN + col]           = acc[ni][0] + bias[col];
        xout[row * ATTN + col + 1]       = acc[ni][1] + bias[col + 1];
        xout[(row + 8) * ATTN + col]     = acc[ni][2] + bias[col];
        xout[(row + 8) * ATTN + col + 1] = acc[ni][3] + bias[col + 1];
    }
}

// ---------------------------------------------------------------------------
// Kernel 2: alpha row/col sums with tanh (MUFU-bound; near floor).
// ---------------------------------------------------------------------------
__global__ __launch_bounds__(256) void alpha_kernel(const float* __restrict__ w)
{
    __shared__ float x1s[32][65];
    __shared__ float x2s[32][65];
    __shared__ float wsm[ATTN];
    __shared__ float rowp[64];
    __shared__ float colp[64];

    const int tid = threadIdx.y * 16 + threadIdx.x;
    const int m0 = blockIdx.y * 64;
    const int n0 = blockIdx.x * 64;

    for (int i = tid; i < ATTN; i += 256) wsm[i] = w[i];
    if (tid < 64) { rowp[tid] = 0.0f; colp[tid] = 0.0f; }

    float acc[4][4];
#pragma unroll
    for (int i = 0; i < 4; i++)
#pragma unroll
        for (int j = 0; j < 4; j++) acc[i][j] = 0.0f;

    for (int a0 = 0; a0 < ATTN; a0 += 32) {
        __syncthreads();
#pragma unroll
        for (int it = 0; it < 8; it++) {
            int idx = tid + it * 256;
            int r = idx >> 5;
            int c = idx & 31;
            x1s[c][r] = g_x1[(m0 + r) * ATTN + a0 + c];
            x2s[c][r] = g_x2[(n0 + r) * ATTN + a0 + c];
        }
        __syncthreads();
#pragma unroll 4
        for (int a = 0; a < 32; a++) {
            float wa = wsm[a0 + a];
            float v1[4], v2[4];
#pragma unroll
            for (int i = 0; i < 4; i++) v1[i] = x1s[a][threadIdx.y + 16 * i];
#pragma unroll
            for (int j = 0; j < 4; j++) v2[j] = x2s[a][threadIdx.x + 16 * j];
#pragma unroll
            for (int i = 0; i < 4; i++)
#pragma unroll
                for (int j = 0; j < 4; j++)
                    acc[i][j] += wa * tanh_fast(v1[i] + v2[j]);
        }
    }

    __syncthreads();
#pragma unroll
    for (int i = 0; i < 4; i++) {
        float r = acc[i][0] + acc[i][1] + acc[i][2] + acc[i][3];
        atomicAdd(&rowp[threadIdx.y + 16 * i], r);
    }
#pragma unroll
    for (int j = 0; j < 4; j++) {
        float c = acc[0][j] + acc[1][j] + acc[2][j] + acc[3][j];
        atomicAdd(&colp[threadIdx.x + 16 * j], c);
    }
    __syncthreads();
    if (tid < 64) {
        atomicAdd(&g_rowsum[m0 + tid], rowp[tid]);
    } else if (tid < 128) {
        atomicAdd(&g_colsum[n0 + tid - 64], colp[tid - 64]);
    }
}

// ---------------------------------------------------------------------------
// Kernel 3: fused epilogue. Each block redundantly computes the 768-wide
// softmax (cheap), then does a coalesced 64-row matvec chunk; one
// atomicAdd per (block, column). grid = (12, 2), 256 threads.
// ---------------------------------------------------------------------------
__global__ __launch_bounds__(256) void epilogue_kernel(float* __restrict__ out)
{
    __shared__ float pe[M1];
    __shared__ float red[256];

    const int z   = blockIdx.y;
    const int m0  = blockIdx.x * 64;
    const int tid = threadIdx.x;
    const float* __restrict__ sums = z ? g_colsum : g_rowsum;
    const float* __restrict__ x    = z ? g_x2 : g_x1;

    // ---- softmax over sums / 768 (redundant across blocks with same z) ----
    float v[3];
    float lmax = -1e30f;
#pragma unroll
    for (int j = 0; j < 3; j++) {
        v[j] = sums[tid + j * 256] * (1.0f / 768.0f);
        lmax = fmaxf(lmax, v[j]);
    }
    red[tid] = lmax;
    __syncthreads();
    for (int s = 128; s > 0; s >>= 1) {
        if (tid < s) red[tid] = fmaxf(red[tid], red[tid + s]);
        __syncthreads();
    }
    const float mx = red[0];
    __syncthreads();
    float lsum = 0.0f;
#pragma unroll
    for (int j = 0; j < 3; j++) {
        float e = __expf(v[j] - mx);
        pe[tid + j * 256] = e;
        lsum += e;
    }
    red[tid] = lsum;
    __syncthreads();
    for (int s = 128; s > 0; s >>= 1) {
        if (tid < s) red[tid] += red[tid + s];
        __syncthreads();
    }
    const float inv = 1.0f / red[0];
    __syncthreads();

    // ---- matvec chunk: rows m0..m0+63, thread = column (coalesced) ----
    const int a = tid;
    float s0 = 0.0f, s1 = 0.0f, s2 = 0.0f, s3 = 0.0f;
#pragma unroll 4
    for (int m = 0; m < 64; m += 4) {
        s0 += x[(m0 + m + 0) * ATTN + a] * pe[m0 + m + 0];
        s1 += x[(m0 + m + 1) * ATTN + a] * pe[m0 + m + 1];
        s2 += x[(m0 + m + 2) * ATTN + a] * pe[m0 + m + 2];
        s3 += x[(m0 + m + 3) * ATTN + a] * pe[m0 + m + 3];
    }
    atomicAdd(&out[z * ATTN + a], ((s0 + s1) + (s2 + s3)) * inv);
}

extern "C" void kernel_launch(void* const* d_in, const int* in_sizes, int n_in,
                              void* d_out, int out_size)
{
    const float* h1 = (const float*)d_in[0];
    const float* h2 = (const float*)d_in[1];
    const float* W1 = (const float*)d_in[2];
    const float* b1 = (const float*)d_in[3];
    const float* W2 = (const float*)d_in[4];
    const float* b2 = (const float*)d_in[5];
    const float* w  = (const float*)d_in[6];
    float* out = (float*)d_out;

    cudaFuncSetAttribute(gemm_kernel, cudaFuncAttributeMaxDynamicSharedMemorySize, GEMM_SMEM_BYTES);

    convert_kernel<<<1536, 512>>>(h1, h2, W1, W2, out);
    gemm_kernel<<<dim3(ATTN / 64, M1 / 64, 2), 256, GEMM_SMEM_BYTES>>>(b1, b2);
    alpha_kernel<<<dim3(M2 / 64, M1 / 64), dim3(16, 16)>>>(w);
    epilogue_kernel<<<dim3(M1 / 64, 2), 256>>>(out);
}

// round 9
// speedup vs baseline: 1.7409x; 1.0214x over previous
#include <cuda_runtime.h>
#include <cuda_bf16.h>
#include <cuda_fp16.h>
#include <cstdint>

#define M1 768
#define M2 768
#define HID 1024
#define ATTN 256

// ---------------- scratch (no cudaMalloc allowed) ----------------
__device__ float g_x1[M1 * ATTN];
__device__ float g_x2[M2 * ATTN];
__device__ __align__(4) __half2 g_x1h[M1 * ATTN / 2];
__device__ __align__(4) __half2 g_x2h[M2 * ATTN / 2];
__device__ float g_rowsum[M1];
__device__ float g_colsum[M2];
__device__ __align__(16) __nv_bfloat16 g_h_hi[2][M1 * HID];
__device__ __align__(16) __nv_bfloat16 g_h_lo[2][M1 * HID];
__device__ __align__(16) __nv_bfloat16 g_w_hi[2][ATTN * HID];
__device__ __align__(16) __nv_bfloat16 g_w_lo[2][ATTN * HID];

// ---------------- helpers ----------------
__device__ __forceinline__ uint32_t smem_to_u32(const void* p) {
    uint32_t a;
    asm("{ .reg .u64 t; cvta.to.shared.u64 t, %1; cvt.u32.u64 %0, t; }" : "=r"(a) : "l"(p));
    return a;
}
__device__ __forceinline__ __half2 tanh2_fast(__half2 x) {
    __half2 r;
    asm("tanh.approx.f16x2 %0, %1;" : "=r"(*(uint32_t*)&r) : "r"(*(const uint32_t*)&x));
    return r;
}

#define CP_ASYNC_16(dst, src) \
    asm volatile("cp.async.cg.shared.global [%0], [%1], 16;" :: "r"(dst), "l"(src) : "memory")
#define CP_ASYNC_COMMIT() asm volatile("cp.async.commit_group;" ::: "memory")
#define CP_ASYNC_WAIT(n)  asm volatile("cp.async.wait_group %0;" :: "n"(n) : "memory")

#define LDSM_X4(r0, r1, r2, r3, addr) \
    asm volatile("ldmatrix.sync.aligned.m8n8.x4.shared.b16 {%0,%1,%2,%3}, [%4];" \
                 : "=r"(r0), "=r"(r1), "=r"(r2), "=r"(r3) : "r"(addr))
// B tile is [n][k] with k contiguous (== col-major B for mma row.col):
// NON-transposed ldmatrix yields exactly the mma B fragment mapping.
#define LDSM_X2(r0, r1, addr) \
    asm volatile("ldmatrix.sync.aligned.m8n8.x2.shared.b16 {%0,%1}, [%2];" \
                 : "=r"(r0), "=r"(r1) : "r"(addr))

#define MMA_16816(d0, d1, d2, d3, a0, a1, a2, a3, b0, b1) \
    asm volatile("mma.sync.aligned.m16n8k16.row.col.f32.bf16.bf16.f32 " \
                 "{%0,%1,%2,%3}, {%4,%5,%6,%7}, {%8,%9}, {%0,%1,%2,%3};" \
                 : "+f"(d0), "+f"(d1), "+f"(d2), "+f"(d3) \
                 : "r"(a0), "r"(a1), "r"(a2), "r"(a3), "r"(b0), "r"(b1))

// ---------------------------------------------------------------------------
// Kernel 0: fp32 -> bf16 hi/lo split; zero reduction scratch and d_out.
// ---------------------------------------------------------------------------
__global__ __launch_bounds__(512) void convert_kernel(
    const float* __restrict__ h1, const float* __restrict__ h2,
    const float* __restrict__ W1, const float* __restrict__ W2,
    float* __restrict__ out)
{
    if (blockIdx.x == 0) {
        for (int j = threadIdx.x; j < M1; j += blockDim.x) { g_rowsum[j] = 0.0f; g_colsum[j] = 0.0f; }
        out[threadIdx.x] = 0.0f;   // out_size == 512, poisoned by harness
    }
    const int i = blockIdx.x * blockDim.x + threadIdx.x;   // 0 .. 786431
    {
        float x = h1[i];
        __nv_bfloat16 hi = __float2bfloat16(x);
        g_h_hi[0][i] = hi;
        g_h_lo[0][i] = __float2bfloat16(x - __bfloat162float(hi));
        x = h2[i];
        hi = __float2bfloat16(x);
        g_h_hi[1][i] = hi;
        g_h_lo[1][i] = __float2bfloat16(x - __bfloat162float(hi));
    }
    if (i < ATTN * HID) {
        float x = W1[i];
        __nv_bfloat16 hi = __float2bfloat16(x);
        g_w_hi[0][i] = hi;
        g_w_lo[0][i] = __float2bfloat16(x - __bfloat162float(hi));
        x = W2[i];
        hi = __float2bfloat16(x);
        g_w_hi[1][i] = hi;
        g_w_lo[1][i] = __float2bfloat16(x - __bfloat162float(hi));
    }
}

// ---------------------------------------------------------------------------
// Kernel 1: bf16 mma.sync GEMM, 3-term hi/lo compensation.
// Block tile 64x64, K-chunk 64, 8 warps @ 16x32, cp.async dbl-buf, 96 CTAs.
// Writeback emits f32 (epilogue) AND packed fp16 (alpha) copies.
// ---------------------------------------------------------------------------
#define AROW 144
#define SZ_T (64 * AROW)
#define BUF_SZ (4 * SZ_T)
#define GEMM_SMEM_BYTES (2 * BUF_SZ + 16)

__global__ __launch_bounds__(256) void gemm_kernel(
    const float* __restrict__ bias1, const float* __restrict__ bias2)
{
    extern __shared__ char dsm[];
    const uint32_t smem = smem_to_u32(dsm);

    const int tid  = threadIdx.x;
    const int lane = tid & 31;
    const int wid  = tid >> 5;
    const int wm   = wid & 3;
    const int wn   = wid >> 2;

    const int z  = blockIdx.z;
    const int m0 = blockIdx.y * 64;
    const int a0 = blockIdx.x * 64;

    const __nv_bfloat16* __restrict__ Ahg = g_h_hi[z];
    const __nv_bfloat16* __restrict__ Alg = g_h_lo[z];
    const __nv_bfloat16* __restrict__ Bhg = g_w_hi[z];
    const __nv_bfloat16* __restrict__ Blg = g_w_lo[z];
    const float* __restrict__ bias = z ? bias2 : bias1;
    float* __restrict__ xout = z ? g_x2 : g_x1;
    __half2* __restrict__ xouth = z ? g_x2h : g_x1h;

    auto load_chunk = [&](int c) {
        const int k0 = c * 64;
        const uint32_t buf = smem + (c & 1) * BUF_SZ;
#pragma unroll
        for (int it = 0; it < 2; it++) {
            const int s = tid + it * 256;
            const int r = s >> 3, cc = s & 7;
            const uint32_t so = r * AROW + cc * 16;
            CP_ASYNC_16(buf + so,              Ahg + (m0 + r) * HID + k0 + cc * 8);
            CP_ASYNC_16(buf + SZ_T + so,       Alg + (m0 + r) * HID + k0 + cc * 8);
            CP_ASYNC_16(buf + 2 * SZ_T + so,   Bhg + (a0 + r) * HID + k0 + cc * 8);
            CP_ASYNC_16(buf + 3 * SZ_T + so,   Blg + (a0 + r) * HID + k0 + cc * 8);
        }
        CP_ASYNC_COMMIT();
    };

    float acc[4][4];
#pragma unroll
    for (int ni = 0; ni < 4; ni++)
#pragma unroll
        for (int q = 0; q < 4; q++) acc[ni][q] = 0.0f;

    const uint32_t a_lane_off = (wm * 16 + (lane & 15)) * AROW + ((lane >> 4) * 16);
    const uint32_t b_lane_off = (wn * 32 + (lane & 7)) * AROW + (((lane >> 3) & 1) * 16);

    load_chunk(0);

    for (int c = 0; c < 16; c++) {
        if (c + 1 < 16) {
            load_chunk(c + 1);
            CP_ASYNC_WAIT(1);
        } else {
            CP_ASYNC_WAIT(0);
        }
        __syncthreads();

        const uint32_t buf = smem + (c & 1) * BUF_SZ;
        const uint32_t sAh = buf + a_lane_off;
        const uint32_t sAl = buf + SZ_T + a_lane_off;
        const uint32_t sBh = buf + 2 * SZ_T + b_lane_off;
        const uint32_t sBl = buf + 3 * SZ_T + b_lane_off;

#pragma unroll
        for (int ks = 0; ks < 4; ks++) {
            const uint32_t kb = ks * 32;
            uint32_t ah[4], al[4], bh[4][2], bl[4][2];
            LDSM_X4(ah[0], ah[1], ah[2], ah[3], sAh + kb);
            LDSM_X4(al[0], al[1], al[2], al[3], sAl + kb);
#pragma unroll
            for (int ni = 0; ni < 4; ni++) {
                LDSM_X2(bh[ni][0], bh[ni][1], sBh + ni * (8 * AROW) + kb);
                LDSM_X2(bl[ni][0], bl[ni][1], sBl + ni * (8 * AROW) + kb);
            }
#pragma unroll
            for (int ni = 0; ni < 4; ni++) {
                MMA_16816(acc[ni][0], acc[ni][1], acc[ni][2], acc[ni][3],
                          ah[0], ah[1], ah[2], ah[3], bh[ni][0], bh[ni][1]);
                MMA_16816(acc[ni][0], acc[ni][1], acc[ni][2], acc[ni][3],
                          ah[0], ah[1], ah[2], ah[3], bl[ni][0], bl[ni][1]);
                MMA_16816(acc[ni][0], acc[ni][1], acc[ni][2], acc[ni][3],
                          al[0], al[1], al[2], al[3], bh[ni][0], bh[ni][1]);
            }
        }
        __syncthreads();
    }

    const int row = m0 + wm * 16 + (lane >> 2);
#pragma unroll
    for (int ni = 0; ni < 4; ni++) {
        const int col = a0 + wn * 32 + ni * 8 + (lane & 3) * 2;   // even
        const float v0 = acc[ni][0] + bias[col];
        const float v1 = acc[ni][1] + bias[col + 1];
        const float v2 = acc[ni][2] + bias[col];
        const float v3 = acc[ni][3] + bias[col + 1];
        xout[row * ATTN + col]           = v0;
        xout[row * ATTN + col + 1]       = v1;
        xout[(row + 8) * ATTN + col]     = v2;
        xout[(row + 8) * ATTN + col + 1] = v3;
        xouth[row * (ATTN / 2) + (col >> 1)]       = __floats2half2_rn(v0, v1);
        xouth[(row + 8) * (ATTN / 2) + (col >> 1)] = __floats2half2_rn(v2, v3);
    }
}

// ---------------------------------------------------------------------------
// Kernel 2: alpha row/col sums, fp16x2 tanh (2 tanh per MUFU op).
// Tile 64m x 64n, a processed as 128 half2 pairs in 8 chunks of 16.
// ---------------------------------------------------------------------------
__global__ __launch_bounds__(256) void alpha_kernel(const float* __restrict__ w)
{
    __shared__ __half2 x1s[16][66];   // [pair][m], pad 66 (bank-spread)
    __shared__ __half2 x2s[16][66];
    __shared__ float wsm[ATTN];
    __shared__ float rowp[64];
    __shared__ float colp[64];

    const int tx = threadIdx.x;       // n
    const int ty = threadIdx.y;       // m
    const int tid = ty * 16 + tx;
    const int m0 = blockIdx.y * 64;
    const int n0 = blockIdx.x * 64;

    for (int i = tid; i < ATTN; i += 256) wsm[i] = w[i];
    if (tid < 64) { rowp[tid] = 0.0f; colp[tid] = 0.0f; }

    float acc[4][4];
#pragma unroll
    for (int i = 0; i < 4; i++)
#pragma unroll
        for (int j = 0; j < 4; j++) acc[i][j] = 0.0f;

    for (int a0h = 0; a0h < ATTN / 2; a0h += 16) {
        __syncthreads();
#pragma unroll
        for (int it = 0; it < 4; it++) {
            const int idx = tid + it * 256;   // 0..1023
            const int p = idx & 15;
            const int r = idx >> 4;           // 0..63
            x1s[p][r] = g_x1h[(m0 + r) * (ATTN / 2) + a0h + p];
            x2s[p][r] = g_x2h[(n0 + r) * (ATTN / 2) + a0h + p];
        }
        __syncthreads();
#pragma unroll 2
        for (int p = 0; p < 16; p++) {
            const float wlo = wsm[(a0h + p) * 2];
            const float whi = wsm[(a0h + p) * 2 + 1];
            __half2 v1[4], v2[4];
#pragma unroll
            for (int i = 0; i < 4; i++) v1[i] = x1s[p][ty + 16 * i];
#pragma unroll
            for (int j = 0; j < 4; j++) v2[j] = x2s[p][tx + 16 * j];
#pragma unroll
            for (int i = 0; i < 4; i++)
#pragma unroll
                for (int j = 0; j < 4; j++) {
                    const __half2 t = tanh2_fast(__hadd2(v1[i], v2[j]));
                    const float2 f = __half22float2(t);
                    acc[i][j] = fmaf(wlo, f.x, fmaf(whi, f.y, acc[i][j]));
                }
        }
    }

    __syncthreads();
#pragma unroll
    for (int i = 0; i < 4; i++) {
        float r = acc[i][0] + acc[i][1] + acc[i][2] + acc[i][3];
        atomicAdd(&rowp[ty + 16 * i], r);
    }
#pragma unroll
    for (int j = 0; j < 4; j++) {
        float c = acc[0][j] + acc[1][j] + acc[2][j] + acc[3][j];
        atomicAdd(&colp[tx + 16 * j], c);
    }
    __syncthreads();
    if (tid < 64) {
        atomicAdd(&g_rowsum[m0 + tid], rowp[tid]);
    } else if (tid < 128) {
        atomicAdd(&g_colsum[n0 + tid - 64], colp[tid - 64]);
    }
}

// ---------------------------------------------------------------------------
// Kernel 3: fused epilogue (redundant softmax + coalesced matvec chunk).
// ---------------------------------------------------------------------------
__global__ __launch_bounds__(256) void epilogue_kernel(float* __restrict__ out)
{
    __shared__ float pe[M1];
    __shared__ float red[256];

    const int z   = blockIdx.y;
    const int m0  = blockIdx.x * 64;
    const int tid = threadIdx.x;
    const float* __restrict__ sums = z ? g_colsum : g_rowsum;
    const float* __restrict__ x    = z ? g_x2 : g_x1;

    float v[3];
    float lmax = -1e30f;
#pragma unroll
    for (int j = 0; j < 3; j++) {
        v[j] = sums[tid + j * 256] * (1.0f / 768.0f);
        lmax = fmaxf(lmax, v[j]);
    }
    red[tid] = lmax;
    __syncthreads();
    for (int s = 128; s > 0; s >>= 1) {
        if (tid < s) red[tid] = fmaxf(red[tid], red[tid + s]);
        __syncthreads();
    }
    const float mx = red[0];
    __syncthreads();
    float lsum = 0.0f;
#pragma unroll
    for (int j = 0; j < 3; j++) {
        float e = __expf(v[j] - mx);
        pe[tid + j * 256] = e;
        lsum += e;
    }
    red[tid] = lsum;
    __syncthreads();
    for (int s = 128; s > 0; s >>= 1) {
        if (tid < s) red[tid] += red[tid + s];
        __syncthreads();
    }
    const float inv = 1.0f / red[0];
    __syncthreads();

    const int a = tid;
    float s0 = 0.0f, s1 = 0.0f, s2 = 0.0f, s3 = 0.0f;
#pragma unroll 4
    for (int m = 0; m < 64; m += 4) {
        s0 += x[(m0 + m + 0) * ATTN + a] * pe[m0 + m + 0];
        s1 += x[(m0 + m + 1) * ATTN + a] * pe[m0 + m + 1];
        s2 += x[(m0 + m + 2) * ATTN + a] * pe[m0 + m + 2];
        s3 += x[(m0 + m + 3) * ATTN + a] * pe[m0 + m + 3];
    }
    atomicAdd(&out[z * ATTN + a], ((s0 + s1) + (s2 + s3)) * inv);
}

extern "C" void kernel_launch(void* const* d_in, const int* in_sizes, int n_in,
                              void* d_out, int out_size)
{
    const float* h1 = (const float*)d_in[0];
    const float* h2 = (const float*)d_in[1];
    const float* W1 = (const float*)d_in[2];
    const float* b1 = (const float*)d_in[3];
    const float* W2 = (const float*)d_in[4];
    const float* b2 = (const float*)d_in[5];
    const float* w  = (const float*)d_in[6];
    float* out = (float*)d_out;

    cudaFuncSetAttribute(gemm_kernel, cudaFuncAttributeMaxDynamicSharedMemorySize, GEMM_SMEM_BYTES);

    convert_kernel<<<1536, 512>>>(h1, h2, W1, W2, out);
    gemm_kernel<<<dim3(ATTN / 64, M1 / 64, 2), 256, GEMM_SMEM_BYTES>>>(b1, b2);
    alpha_kernel<<<dim3(M2 / 64, M1 / 64), dim3(16, 16)>>>(w);
    epilogue_kernel<<<dim3(M1 / 64, 2), 256>>>(out);
}